// round 11
// baseline (speedup 1.0000x reference)
#include <cuda_runtime.h>

#define EB     128
#define NTH    512
#define H_STR  101
#define F_STR  73
#define Y_STR  26
#define T_STR  41
#define WSH_PAD 10112
#define DPI    3.14159265358979323846
#define CGB    154          // CG blocks in prep kernel (8 warps each -> 1232 warps >= 1225)
#define ZB     704          // zeroing blocks in prep kernel

// ---------------- device globals (scratch, no allocation) ----------------
__device__ float g_CG[1225];
__device__ float g_K[25];
__device__ float g_norm[3];

// 19 tensor-product instances: (lo, li, l) with kk = index of l within the pair
__constant__ int c_lo[19]   = {0,0,0,1,1,1,1,1,1,1,2,2,2,2,2,2,2,2,2};
__constant__ int c_li[19]   = {0,1,2,0,1,1,1,2,2,2,0,1,1,1,2,2,2,2,2};
__constant__ int c_l [19]   = {0,1,2,1,0,1,2,1,2,3,2,1,2,3,0,1,2,3,4};
__constant__ int c_kk[19]   = {0,0,0,0,0,1,2,0,1,2,0,0,1,2,0,1,2,3,4};
__constant__ int c_roff[19] = {0,64,128,192,256,256,256,448,448,448,640,704,704,704,896,896,896,896,896};
__constant__ int c_foff[19] = {0,8,32,0,8,8,8,32,32,32,0,8,8,8,32,32,32,32,32};
__constant__ int c_cgoff[19]= {0,1,10,35,44,53,80,125,170,245,350,375,420,495,600,625,700,825,1000};
__constant__ int c_nl[19]   = {1,1,1,1,3,3,3,3,3,3,1,3,3,3,5,5,5,5,5};

// ---------------- packed f32x2 helpers (Blackwell FFMA2) ----------------
union F2U { unsigned long long u; float2 f; };

__device__ __forceinline__ unsigned long long pack2(float a){
    unsigned long long r;
    asm("mov.b64 %0, {%1, %1};" : "=l"(r) : "r"(__float_as_uint(a)));
    return r;
}
__device__ __forceinline__ void ffma2(unsigned long long& d,
                                      unsigned long long a, unsigned long long b){
    asm("fma.rn.f32x2 %0, %1, %2, %0;" : "+l"(d) : "l"(a), "l"(b));
}

// ---------------- CG helpers ----------------
__device__ double dfact_s(int n){ double r=1.0; for(int i=2;i<=n;i++) r*=(double)i; return r; }

// w3j with precomputed factorial table (selection rules guaranteed by caller)
__device__ double w3j_t(const double* ft,int j1,int j2,int j3,int m1,int m2,int m3){
    double pre = sqrt( ft[j1+j2-j3]*ft[j1-j2+j3]*ft[-j1+j2+j3]/ft[j1+j2+j3+1]
                     * ft[j1+m1]*ft[j1-m1]*ft[j2+m2]*ft[j2-m2]
                     * ft[j3+m3]*ft[j3-m3] );
    int kmin = max(0, max(j2-j3-m1, j1-j3+m2));
    int kmax = min(j1+j2-j3, min(j1-m1, j2+m2));
    double s = 0.0;
    for (int k=kmin;k<=kmax;k++){
        double den = ft[k]*ft[j1+j2-j3-k]*ft[j1-m1-k]*ft[j2+m2-k]
                   * ft[j3-j2+m1+k]*ft[j3-j1-m2+k];
        s += ((k&1)?-1.0:1.0)/den;
    }
    int ex = j1-j2-m3;
    double sgn = (ex & 1) ? -1.0 : 1.0;
    return sgn*pre*s;
}

// complex->real SH change-of-basis: row a (0..2l), complex col index m (-l..l)
__device__ void u_c2r(int l, int a, int m, double& re, double& im){
    re = 0.0; im = 0.0;
    const double is2 = 0.70710678118654752440;
    if (a == l){ if (m == 0) re = 1.0; return; }
    if (a > l){
        int mm = a - l;
        if      (m ==  mm) re = ((mm&1)?-1.0:1.0)*is2;
        else if (m == -mm) re = is2;
    } else {
        int mm = l - a;
        if      (m == -mm) im = is2;
        else if (m ==  mm) im = -((mm&1)?-1.0:1.0)*is2;
    }
}

// ---------------- merged prep kernel: CG init (warp per element) + zero(out) ----------------
__global__ void prep_kernel(float* __restrict__ out, int out_size){
    if (blockIdx.x < CGB){
        if (blockIdx.x == 0 && threadIdx.x < 28){
            int idx = threadIdx.x;
            if (idx < 25){
                int l = 0; while ((l+1)*(l+1) <= idx) l++;
                int m = idx - l*l - l;
                int am = m < 0 ? -m : m;
                double K = sqrt((2.0*l+1.0)/(4.0*DPI) * dfact_s(l-am)/dfact_s(l+am));
                if (m != 0) K *= sqrt(2.0);
                g_K[idx] = (float)K;
            } else {
                int lo = idx - 25;
                int nse = (lo==0)?24:(lo==1?56:72);
                g_norm[lo] = (float)(sqrt(4.0*DPI)*sqrt(2.0*lo+1.0)/sqrt((double)nse));
            }
        }

        // one warp per CG element; lanes parallelize the (m1,m2) terms
        int e    = blockIdx.x*8 + (threadIdx.x >> 5);
        int lane = threadIdx.x & 31;
        if (e < 1225){
            double ft[10];
            ft[0] = 1.0;
            #pragma unroll
            for (int i=1;i<10;i++) ft[i] = ft[i-1]*(double)i;

            int inst = 0;
            for (int i2=1;i2<19;i2++) if (e >= c_cgoff[i2]) inst = i2;
            int lo = c_lo[inst], li = c_li[inst], l3 = c_l[inst];
            int n1 = 2*lo+1, n2 = 2*li+1, Rd = 2*l3+1;
            int off = e - c_cgoff[inst];
            int a = off/(n2*Rd);
            int rem = off - a*n2*Rd;
            int b = rem/Rd;
            int c = rem - b*Rd;

            double t = 0.0;
            if (lane < n1*n2){
                int m1 = lane/n2 - lo;
                int m2 = lane%n2 - li;
                int m3 = -(m1+m2);
                if (m3 >= -l3 && m3 <= l3){
                    double u1r,u1i,u2r,u2i,u3r,u3i;
                    u_c2r(lo,a,m1,u1r,u1i);
                    u_c2r(li,b,m2,u2r,u2i);
                    u_c2r(l3,c,m3,u3r,u3i);
                    bool nz1 = (u1r!=0.0)||(u1i!=0.0);
                    bool nz2 = (u2r!=0.0)||(u2i!=0.0);
                    bool nz3 = (u3r!=0.0)||(u3i!=0.0);
                    if (nz1 && nz2 && nz3){
                        double w = w3j_t(ft, lo,li,l3,m1,m2,m3);
                        double p12r = u1r*u2r - u1i*u2i;
                        double p12i = u1r*u2i + u1i*u2r;
                        double pr = p12r*u3r - p12i*u3i;
                        double pi = p12r*u3i + p12i*u3r;
                        t = (pr + pi)*w;
                    }
                }
            }
            #pragma unroll
            for (int o=16;o>0;o>>=1) t += __shfl_down_sync(0xffffffffu, t, o);
            if (lane == 0) g_CG[e] = (float)t;
        }
    } else {
        float4 z = make_float4(0.f,0.f,0.f,0.f);
        int n4 = out_size >> 2;
        int stride = (gridDim.x - CGB)*blockDim.x;
        for (int i4 = (blockIdx.x - CGB)*blockDim.x + threadIdx.x; i4 < n4; i4 += stride)
            reinterpret_cast<float4*>(out)[i4] = z;
        if (blockIdx.x == CGB && threadIdx.x < (out_size & 3))
            out[(n4<<2) + threadIdx.x] = 0.f;
    }
}

// ---------------- MLP layer with f32x2: dst[e][o] = silu(sum_k src[e][k]*Wsh[k][o]) ----
// 512 threads: wid16 = tid>>5 handles col pairs {wid16*2 + 32*j, +1}, j=0..3;
// lane handles 4 edges (lane, +32, +64, +96). Pairs even-aligned -> LDS.64 on W.
// Wsh pad region zeroed, so over-read columns (>=100) contribute 0 via guarded writes.
__device__ __forceinline__ void mlp_layer(const float* __restrict__ src, float* __restrict__ dst,
                                          const float* __restrict__ Wsh, int lane, int wid16, int K){
    unsigned long long acc[4][4];
    #pragma unroll
    for (int i=0;i<4;i++)
        #pragma unroll
        for (int j=0;j<4;j++) acc[i][j] = 0ull;
    const int cb = wid16*2;
    for (int k=0;k<K;k++){
        unsigned long long hh0 = pack2(src[ lane      *H_STR + k]);
        unsigned long long hh1 = pack2(src[(lane+32)  *H_STR + k]);
        unsigned long long hh2 = pack2(src[(lane+64)  *H_STR + k]);
        unsigned long long hh3 = pack2(src[(lane+96)  *H_STR + k]);
        #pragma unroll
        for (int j=0;j<4;j++){
            unsigned long long w = *(const unsigned long long*)&Wsh[k*100 + cb + 32*j];
            ffma2(acc[0][j], hh0, w);
            ffma2(acc[1][j], hh1, w);
            ffma2(acc[2][j], hh2, w);
            ffma2(acc[3][j], hh3, w);
        }
    }
    #pragma unroll
    for (int i=0;i<4;i++)
        #pragma unroll
        for (int j=0;j<4;j++){
            int c = cb + 32*j;
            F2U cv; cv.u = acc[i][j];
            if (c < 100){
                float v = cv.f.x;
                dst[(lane + 32*i)*H_STR + c] = v / (1.f + __expf(-v));
            }
            if (c + 1 < 100){
                float v = cv.f.y;
                dst[(lane + 32*i)*H_STR + c + 1] = v / (1.f + __expf(-v));
            }
        }
}

// prefetch next W3 tile into registers (13 per thread); flat i = tid + j*512,
// k = i>>6, c = i&63, value = W3[k*1216 + roff + c*nl + kk] / sqrt(100)
__device__ __forceinline__ void w3_prefetch(const float* __restrict__ W3, int inst,
                                            int tid, float* wreg){
    const int roff = c_roff[inst], nl = c_nl[inst], kk = c_kk[inst];
    #pragma unroll
    for (int j=0;j<13;j++){
        int i = tid + j*NTH;
        if (i < 6400){
            int k = i >> 6, c = i & 63;
            wreg[j] = W3[k*1216 + roff + c*nl + kk] * 0.1f;
        }
    }
}

// ---------------- main fused kernel ----------------
__global__ void __launch_bounds__(NTH, 1)
tfn_main(const int* __restrict__ ei, const float* __restrict__ x,
         const float* __restrict__ dist, const float* __restrict__ rvec,
         const float* __restrict__ W0, const float* __restrict__ W1,
         const float* __restrict__ W2, const float* __restrict__ W3,
         float* __restrict__ out, int E)
{
    extern __shared__ float sm[];
    float* A   = sm;                    // [128][101]  h1 / h3
    float* B   = A   + EB*H_STR;        // [128][101]  h0 / h2
    float* Wsh = B   + EB*H_STR;        // WSH_PAD floats: W0/W1/W2 staged; then W3 tile [100][64]
    float* F   = Wsh + WSH_PAD;         // [128][73]
    float* Ysh = F   + EB*F_STR;        // [128][26]
    float* T   = Ysh + EB*Y_STR;        // [128][41]
    float* CGs = T   + EB*T_STR;        // 1225 (padded 1232)
    int*  DST  = (int*)(CGs + 1232);    // [128]

    const int tid   = threadIdx.x;
    const int lane  = tid & 31;
    const int wid16 = tid >> 5;         // 0..15
    const int u     = wid16 & 7;        // output-mult column group
    const int eh    = wid16 >> 3;       // edge half (0: edges 0-63, 1: edges 64-127)
    const int base  = blockIdx.x * EB;
    const int e_act = min(EB, E - base);

    // per-thread message accumulators: 2 edges x 9 cols (rep0:1, rep1:3, rep2:5) for this u
    float msg_acc[2][9];
    #pragma unroll
    for (int i=0;i<2;i++)
        #pragma unroll
        for (int s=0;s<9;s++) msg_acc[i][s] = 0.f;

    // ---- stage S0: W0 (+zero pad), CG, basis -> B, spherical harmonics, F gather ----
    for (int i = tid; i < 1000; i += NTH) Wsh[i] = W0[i] * 0.31622776601683794f; // /sqrt(10)
    for (int i = 10000 + tid; i < WSH_PAD; i += NTH) Wsh[i] = 0.f;               // pad
    for (int i = tid; i < 1225; i += NTH) CGs[i] = g_CG[i];

    if (tid < EB){
        int e = tid;
        bool act = (e < e_act);
        DST[e] = act ? ei[E + base + e] : 0;

        // gaussian basis
        float d = act ? dist[base + e] : 0.f;
        #pragma unroll
        for (int k=0;k<10;k++){
            float c = 0.7f + (2.5f/9.f)*(float)k;
            float t = (d - c) * 4.5f;                       // 1/sigma = 9/(0.8*2.5)
            B[e*H_STR + k] = act ? __expf(-t*t) * (1.f/1.423085244900308f) : 0.f;
        }

        // spherical harmonics (lmax=4), matching reference recurrences
        float vx=0.f, vy=0.f, vz=0.f;
        if (act){ vx = rvec[(base+e)*3]; vy = rvec[(base+e)*3+1]; vz = rvec[(base+e)*3+2]; }
        float r   = sqrtf(vx*vx + vy*vy + vz*vz);
        float inv = 1.f / fmaxf(r, 1e-9f);
        float X = vx*inv, Yc = vy*inv, Z = vz*inv;
        float Am[5], Bm[5];
        Am[0] = 1.f; Bm[0] = 0.f;
        #pragma unroll
        for (int m=1;m<=4;m++){
            Am[m] = X*Am[m-1] - Yc*Bm[m-1];
            Bm[m] = X*Bm[m-1] + Yc*Am[m-1];
        }
        float P[5][5];
        P[0][0] = 1.f;
        #pragma unroll
        for (int m=0;m<=4;m++){
            if (m > 0) P[m][m] = -(2.f*m - 1.f)*P[m-1][m-1];
            if (m < 4) P[m+1][m] = (2.f*m + 1.f)*Z*P[m][m];
            #pragma unroll
            for (int l=m+2;l<=4;l++)
                P[l][m] = ((2.f*l - 1.f)*Z*P[l-1][m] - (l + m - 1.f)*P[l-2][m]) / (float)(l - m);
        }
        if (act){
            int idx = 0;
            #pragma unroll
            for (int l=0;l<=4;l++){
                #pragma unroll
                for (int m=-l;m<=l;m++,idx++){
                    int am = (m < 0) ? -m : m;
                    float K = g_K[idx];
                    float val = (m == 0) ? K*P[l][0]
                              : (m > 0)  ? K*P[l][m]*Am[m]
                                         : K*P[l][am]*Bm[am];
                    Ysh[e*Y_STR + idx] = val;
                }
            }
        } else {
            for (int idx=0; idx<25; idx++) Ysh[e*Y_STR + idx] = 0.f;
        }
    }

    // F = x[src]
    for (int i = tid; i < EB*72; i += NTH){
        int e = i/72, dcol = i - e*72;
        float v = 0.f;
        if (e < e_act){ int s = ei[base + e]; v = x[s*72 + dcol]; }
        F[e*F_STR + dcol] = v;
    }
    __syncthreads();

    // prefetch W3 tile for instance 0 (LDGs overlap the MLP below)
    float wreg[13];
    w3_prefetch(W3, 0, tid, wreg);

    // ---- MLP: h0(B) -> h1(A) -> h2(B) -> h3(A) ----
    mlp_layer(B, A, Wsh, lane, wid16, 10);
    __syncthreads();
    for (int i = tid; i < 10000; i += NTH) Wsh[i] = W1[i]*0.1f;
    __syncthreads();
    mlp_layer(A, B, Wsh, lane, wid16, 100);
    __syncthreads();
    for (int i = tid; i < 10000; i += NTH) Wsh[i] = W2[i]*0.1f;
    __syncthreads();
    mlp_layer(B, A, Wsh, lane, wid16, 100);
    __syncthreads();

    // ---- phase B: 19 tensor-product instances, fused W3-GEMM + CG contraction ----
    for (int inst = 0; inst < 19; inst++){
        const int lo = c_lo[inst], li = c_li[inst], l = c_l[inst];
        const int P2 = 2*lo+1, Q2 = 2*li+1, Rd = 2*l+1;
        const int foff = c_foff[inst], cgo = c_cgoff[inst];
        const int sbase = (lo == 0) ? 0 : (lo == 1 ? 1 : 4);   // msg_acc slot base
        const float nrm = g_norm[lo];

        // dump prefetched W3 tile to smem: Wsh[i], i = tid + j*512 (= [k][c], k=i>>6, c=i&63)
        #pragma unroll
        for (int j=0;j<13;j++){
            int i = tid + j*NTH;
            if (i < 6400) Wsh[i] = wreg[j];
        }

        // per-edge T[v,p] = sum_q F[v,q] * (sum_r C[p,q,r]*Yl[r])
        // 4 threads per edge (p mod 4 split) -> all 512 threads active
        {
            int e  = tid >> 2;
            int ph = tid & 3;
            if (e < e_act && ph < P2){
                float Yl[9];
                for (int r2=0;r2<Rd;r2++) Yl[r2] = Ysh[e*Y_STR + l*l + r2];
                float Fv[8][5];
                #pragma unroll
                for (int v=0;v<8;v++)
                    #pragma unroll
                    for (int q=0;q<5;q++)
                        Fv[v][q] = (q < Q2) ? F[e*F_STR + foff + v*Q2 + q] : 0.f;
                for (int p=ph;p<P2;p+=4){
                    float Gq[5];
                    #pragma unroll
                    for (int q=0;q<5;q++){
                        float s = 0.f;
                        if (q < Q2)
                            for (int r2=0;r2<Rd;r2++) s += CGs[cgo + (p*Q2 + q)*Rd + r2]*Yl[r2];
                        Gq[q] = s;
                    }
                    #pragma unroll
                    for (int v=0;v<8;v++){
                        float t = 0.f;
                        #pragma unroll
                        for (int q=0;q<5;q++) t += Fv[v][q]*Gq[q];
                        T[e*T_STR + v*P2 + p] = t;
                    }
                }
            }
        }

        // prefetch next instance's W3 tile (overlaps the GEMM below)
        if (inst + 1 < 19) w3_prefetch(W3, inst + 1, tid, wreg);

        __syncthreads();

        // GEMM 128x100x64 with packed f32x2: thread = 2 edges x 8 cols (u, edge-half eh)
        unsigned long long acc2[2][4];
        #pragma unroll
        for (int i=0;i<2;i++)
            #pragma unroll
            for (int j=0;j<4;j++) acc2[i][j] = 0ull;
        const float* wp = &Wsh[u*8];
        const int e0 = lane + 64*eh;
        for (int k=0;k<100;k++){
            unsigned long long hh0 = pack2(A[ e0      *H_STR + k]);
            unsigned long long hh1 = pack2(A[(e0+32)  *H_STR + k]);
            ulonglong2 wA = *(const ulonglong2*)&wp[k*64];      // cols 0-3
            ulonglong2 wB = *(const ulonglong2*)&wp[k*64 + 4];  // cols 4-7
            ffma2(acc2[0][0], hh0, wA.x); ffma2(acc2[0][1], hh0, wA.y);
            ffma2(acc2[0][2], hh0, wB.x); ffma2(acc2[0][3], hh0, wB.y);
            ffma2(acc2[1][0], hh1, wA.x); ffma2(acc2[1][1], hh1, wA.y);
            ffma2(acc2[1][2], hh1, wB.x); ffma2(acc2[1][3], hh1, wB.y);
        }

        // msg_acc[i][sbase+p] += nrm * sum_v R[u,v]*T[v,p]
        #pragma unroll
        for (int i=0;i<2;i++){
            int e = e0 + 32*i;
            if (e < e_act){
                float accf[8];
                #pragma unroll
                for (int j=0;j<4;j++){
                    F2U cv; cv.u = acc2[i][j];
                    accf[2*j]   = cv.f.x;
                    accf[2*j+1] = cv.f.y;
                }
                for (int p=0;p<P2;p++){
                    float s = 0.f;
                    #pragma unroll
                    for (int v=0;v<8;v++) s += accf[v]*T[e*T_STR + v*P2 + p];
                    msg_acc[i][sbase + p] += nrm*s;
                }
            }
        }
        __syncthreads();
    }

    // ---- scatter-add to out[dst]: thread owns cols {u} of its 2 edges ----
    #pragma unroll
    for (int i=0;i<2;i++){
        int e = lane + 64*eh + 32*i;
        if (e < e_act){
            int ob = DST[e]*72;
            atomicAdd(&out[ob + u], msg_acc[i][0]);                       // rep0: col u
            #pragma unroll
            for (int p=0;p<3;p++)
                atomicAdd(&out[ob + 8 + u*3 + p], msg_acc[i][1 + p]);     // rep1
            #pragma unroll
            for (int p=0;p<5;p++)
                atomicAdd(&out[ob + 32 + u*5 + p], msg_acc[i][4 + p]);    // rep2
        }
    }
}

// ---------------- launch ----------------
extern "C" void kernel_launch(void* const* d_in, const int* in_sizes, int n_in,
                              void* d_out, int out_size)
{
    const int*   ei   = (const int*)  d_in[0];
    const float* x    = (const float*)d_in[1];
    const float* dist = (const float*)d_in[2];
    const float* rvec = (const float*)d_in[3];
    const float* W0   = (const float*)d_in[4];
    const float* W1   = (const float*)d_in[5];
    const float* W2   = (const float*)d_in[6];
    const float* W3   = (const float*)d_in[7];
    float* out = (float*)d_out;
    const int E = in_sizes[2];

    size_t smem = (size_t)(EB*H_STR*2 + WSH_PAD + EB*F_STR +
                           EB*Y_STR + EB*T_STR + 1232 + 128)*sizeof(float);
    cudaFuncSetAttribute(tfn_main, cudaFuncAttributeMaxDynamicSharedMemorySize, (int)smem);

    prep_kernel<<<CGB + ZB, 256>>>(out, out_size);
    int nb = (E + EB - 1)/EB;
    tfn_main<<<nb, NTH, smem>>>(ei, x, dist, rvec, W0, W1, W2, W3, out, E);
}

// round 13
// speedup vs baseline: 1.0140x; 1.0140x over previous
#include <cuda_runtime.h>
#include <cuda_bf16.h>
#include <cstdint>

#define EB     128
#define NTH    512
#define H_STR  101
#define F_STR  73
#define Y_STR  26
#define T_STR  41
#define R_STR  68
#define KS     112
#define DPI    3.14159265358979323846
#define CGB    154
#define ZB     704

// smem float offsets
#define OFF_A    0            // 12928: fp32 h1/h3; phase B: Bh/Bl bf16 tiles (64x112 each)
#define OFF_B    12928        // 14336: fp32 h0/h2 (first 12928); phase B: Ah/Al bf16 (128x112 each)
#define OFF_WSH  27264        // 10112: W0/W1/W2 staging; phase B: R [128][68] fp32 (8704)
#define OFF_F    37376        // 9344
#define OFF_Y    46720        // 3328
#define OFF_T    50048        // 5248
#define OFF_CG   55296        // 1232
#define OFF_DST  56528        // 128 ints
#define SM_FLOATS 56672       // 226688 B <= 227 KB

// ---------------- device globals ----------------
__device__ float g_CG[1225];
__device__ float g_K[25];
__device__ float g_norm[3];

__constant__ int c_lo[19]   = {0,0,0,1,1,1,1,1,1,1,2,2,2,2,2,2,2,2,2};
__constant__ int c_li[19]   = {0,1,2,0,1,1,1,2,2,2,0,1,1,1,2,2,2,2,2};
__constant__ int c_l [19]   = {0,1,2,1,0,1,2,1,2,3,2,1,2,3,0,1,2,3,4};
__constant__ int c_kk[19]   = {0,0,0,0,0,1,2,0,1,2,0,0,1,2,0,1,2,3,4};
__constant__ int c_roff[19] = {0,64,128,192,256,256,256,448,448,448,640,704,704,704,896,896,896,896,896};
__constant__ int c_foff[19] = {0,8,32,0,8,8,8,32,32,32,0,8,8,8,32,32,32,32,32};
__constant__ int c_cgoff[19]= {0,1,10,35,44,53,80,125,170,245,350,375,420,495,600,625,700,825,1000};
__constant__ int c_nl[19]   = {1,1,1,1,3,3,3,3,3,3,1,3,3,3,5,5,5,5,5};

// ---------------- warp MMA: m16n8k16 bf16, fp32 accum ----------------
#define MMA_BF16(d, a0,a1,a2,a3, b0,b1) \
    asm volatile("mma.sync.aligned.m16n8k16.row.col.f32.bf16.bf16.f32 " \
        "{%0,%1,%2,%3}, {%4,%5,%6,%7}, {%8,%9}, {%0,%1,%2,%3};" \
        : "+f"((d)[0]),"+f"((d)[1]),"+f"((d)[2]),"+f"((d)[3]) \
        : "r"(a0),"r"(a1),"r"(a2),"r"(a3),"r"(b0),"r"(b1))

// ---------------- packed f32x2 (MLP) ----------------
union F2U { unsigned long long u; float2 f; };
__device__ __forceinline__ unsigned long long pack2(float a){
    unsigned long long r;
    asm("mov.b64 %0, {%1, %1};" : "=l"(r) : "r"(__float_as_uint(a)));
    return r;
}
__device__ __forceinline__ void ffma2(unsigned long long& d, unsigned long long a, unsigned long long b){
    asm("fma.rn.f32x2 %0, %1, %2, %0;" : "+l"(d) : "l"(a), "l"(b));
}

// ---------------- CG helpers + prep kernel (unchanged, passing) ----------------
__device__ double dfact_s(int n){ double r=1.0; for(int i=2;i<=n;i++) r*=(double)i; return r; }
__device__ double w3j_t(const double* ft,int j1,int j2,int j3,int m1,int m2,int m3){
    double pre = sqrt( ft[j1+j2-j3]*ft[j1-j2+j3]*ft[-j1+j2+j3]/ft[j1+j2+j3+1]
                     * ft[j1+m1]*ft[j1-m1]*ft[j2+m2]*ft[j2-m2]*ft[j3+m3]*ft[j3-m3] );
    int kmin = max(0, max(j2-j3-m1, j1-j3+m2));
    int kmax = min(j1+j2-j3, min(j1-m1, j2+m2));
    double s = 0.0;
    for (int k=kmin;k<=kmax;k++){
        double den = ft[k]*ft[j1+j2-j3-k]*ft[j1-m1-k]*ft[j2+m2-k]*ft[j3-j2+m1+k]*ft[j3-j1-m2+k];
        s += ((k&1)?-1.0:1.0)/den;
    }
    int ex = j1-j2-m3;
    return ((ex & 1) ? -1.0 : 1.0)*pre*s;
}
__device__ void u_c2r(int l, int a, int m, double& re, double& im){
    re = 0.0; im = 0.0;
    const double is2 = 0.70710678118654752440;
    if (a == l){ if (m == 0) re = 1.0; return; }
    if (a > l){
        int mm = a - l;
        if      (m ==  mm) re = ((mm&1)?-1.0:1.0)*is2;
        else if (m == -mm) re = is2;
    } else {
        int mm = l - a;
        if      (m == -mm) im = is2;
        else if (m ==  mm) im = -((mm&1)?-1.0:1.0)*is2;
    }
}
__global__ void prep_kernel(float* __restrict__ out, int out_size){
    if (blockIdx.x < CGB){
        if (blockIdx.x == 0 && threadIdx.x < 28){
            int idx = threadIdx.x;
            if (idx < 25){
                int l = 0; while ((l+1)*(l+1) <= idx) l++;
                int m = idx - l*l - l;
                int am = m < 0 ? -m : m;
                double K = sqrt((2.0*l+1.0)/(4.0*DPI) * dfact_s(l-am)/dfact_s(l+am));
                if (m != 0) K *= sqrt(2.0);
                g_K[idx] = (float)K;
            } else {
                int lo = idx - 25;
                int nse = (lo==0)?24:(lo==1?56:72);
                g_norm[lo] = (float)(sqrt(4.0*DPI)*sqrt(2.0*lo+1.0)/sqrt((double)nse));
            }
        }
        int e = blockIdx.x*8 + (threadIdx.x >> 5);
        int lane = threadIdx.x & 31;
        if (e < 1225){
            double ft[10]; ft[0] = 1.0;
            #pragma unroll
            for (int i=1;i<10;i++) ft[i] = ft[i-1]*(double)i;
            int inst = 0;
            for (int i2=1;i2<19;i2++) if (e >= c_cgoff[i2]) inst = i2;
            int lo = c_lo[inst], li = c_li[inst], l3 = c_l[inst];
            int n1 = 2*lo+1, n2 = 2*li+1, Rd = 2*l3+1;
            int off = e - c_cgoff[inst];
            int a = off/(n2*Rd);
            int rem = off - a*n2*Rd;
            int b = rem/Rd;
            int c = rem - b*Rd;
            double t = 0.0;
            if (lane < n1*n2){
                int m1 = lane/n2 - lo, m2 = lane%n2 - li, m3 = -(m1+m2);
                if (m3 >= -l3 && m3 <= l3){
                    double u1r,u1i,u2r,u2i,u3r,u3i;
                    u_c2r(lo,a,m1,u1r,u1i); u_c2r(li,b,m2,u2r,u2i); u_c2r(l3,c,m3,u3r,u3i);
                    if (((u1r!=0.0)||(u1i!=0.0)) && ((u2r!=0.0)||(u2i!=0.0)) && ((u3r!=0.0)||(u3i!=0.0))){
                        double w = w3j_t(ft, lo,li,l3,m1,m2,m3);
                        double p12r = u1r*u2r - u1i*u2i, p12i = u1r*u2i + u1i*u2r;
                        t = ((p12r*u3r - p12i*u3i) + (p12r*u3i + p12i*u3r))*w;
                    }
                }
            }
            #pragma unroll
            for (int o=16;o>0;o>>=1) t += __shfl_down_sync(0xffffffffu, t, o);
            if (lane == 0) g_CG[e] = (float)t;
        }
    } else {
        float4 z = make_float4(0.f,0.f,0.f,0.f);
        int n4 = out_size >> 2;
        int stride = (gridDim.x - CGB)*blockDim.x;
        for (int i4 = (blockIdx.x - CGB)*blockDim.x + threadIdx.x; i4 < n4; i4 += stride)
            reinterpret_cast<float4*>(out)[i4] = z;
        if (blockIdx.x == CGB && threadIdx.x < (out_size & 3))
            out[(n4<<2) + threadIdx.x] = 0.f;
    }
}

// ---------------- MLP layer (R11, passing) ----------------
__device__ __forceinline__ void mlp_layer(const float* __restrict__ src, float* __restrict__ dst,
                                          const float* __restrict__ Wsh, int lane, int wid16, int K){
    unsigned long long acc[4][4];
    #pragma unroll
    for (int i=0;i<4;i++)
        #pragma unroll
        for (int j=0;j<4;j++) acc[i][j] = 0ull;
    const int cb = wid16*2;
    for (int k=0;k<K;k++){
        unsigned long long hh0 = pack2(src[ lane      *H_STR + k]);
        unsigned long long hh1 = pack2(src[(lane+32)  *H_STR + k]);
        unsigned long long hh2 = pack2(src[(lane+64)  *H_STR + k]);
        unsigned long long hh3 = pack2(src[(lane+96)  *H_STR + k]);
        #pragma unroll
        for (int j=0;j<4;j++){
            unsigned long long w = *(const unsigned long long*)&Wsh[k*100 + cb + 32*j];
            ffma2(acc[0][j], hh0, w); ffma2(acc[1][j], hh1, w);
            ffma2(acc[2][j], hh2, w); ffma2(acc[3][j], hh3, w);
        }
    }
    #pragma unroll
    for (int i=0;i<4;i++)
        #pragma unroll
        for (int j=0;j<4;j++){
            int c = cb + 32*j;
            F2U cv; cv.u = acc[i][j];
            if (c < 100){
                float v = cv.f.x;
                dst[(lane + 32*i)*H_STR + c] = v / (1.f + __expf(-v));
            }
            if (c + 1 < 100){
                float v = cv.f.y;
                dst[(lane + 32*i)*H_STR + c + 1] = v / (1.f + __expf(-v));
            }
        }
}

__device__ __forceinline__ void w3_prefetch(const float* __restrict__ W3, int inst,
                                            int tid, float* wreg){
    const int roff = c_roff[inst], nl = c_nl[inst], kk = c_kk[inst];
    #pragma unroll
    for (int j=0;j<13;j++){
        int i = tid + j*NTH;
        if (i < 6400){
            int k = i >> 6, c = i & 63;
            wreg[j] = W3[k*1216 + roff + c*nl + kk] * 0.1f;
        }
    }
}

__device__ __forceinline__ void split_bf16(float v, __nv_bfloat16& h, __nv_bfloat16& l){
    h = __float2bfloat16(v);
    l = __float2bfloat16(v - __bfloat162float(h));
}

// ---------------- main fused kernel ----------------
__global__ void __launch_bounds__(NTH, 1)
tfn_main(const int* __restrict__ ei, const float* __restrict__ x,
         const float* __restrict__ dist, const float* __restrict__ rvec,
         const float* __restrict__ W0, const float* __restrict__ W1,
         const float* __restrict__ W2, const float* __restrict__ W3,
         float* __restrict__ out, int E)
{
    extern __shared__ float sm[];
    float* A   = sm + OFF_A;     // fp32 h1/h3
    float* B   = sm + OFF_B;     // fp32 h0/h2
    float* Wsh = sm + OFF_WSH;   // W staging; later R
    float* R   = sm + OFF_WSH;   // [128][68] fp32 GEMM result
    float* F   = sm + OFF_F;
    float* Ysh = sm + OFF_Y;
    float* T   = sm + OFF_T;
    float* CGs = sm + OFF_CG;
    int*  DST  = (int*)(sm + OFF_DST);

    __nv_bfloat16* Bh = (__nv_bfloat16*)(sm + OFF_A);           // [64][112]
    __nv_bfloat16* Bl = Bh + 64*KS;
    __nv_bfloat16* Ah = (__nv_bfloat16*)(sm + OFF_B);           // [128][112]
    __nv_bfloat16* Al = Ah + 128*KS;

    const int tid   = threadIdx.x;
    const int lane  = tid & 31;
    const int wid16 = tid >> 5;
    const int base  = blockIdx.x * EB;
    const int e_act = min(EB, E - base);

    // per-thread msg accumulators: 1 edge x 2 u x 9 slots
    float msg_acc[2][9];
    #pragma unroll
    for (int i=0;i<2;i++)
        #pragma unroll
        for (int s=0;s<9;s++) msg_acc[i][s] = 0.f;

    // ---- prologue: W0 stage (+pad), CG, basis, SH, F gather ----
    for (int i = tid; i < 1000; i += NTH) Wsh[i] = W0[i] * 0.31622776601683794f;
    for (int i = 10000 + tid; i < 10112; i += NTH) Wsh[i] = 0.f;
    for (int i = tid; i < 1225; i += NTH) CGs[i] = g_CG[i];

    if (tid < EB){
        int e = tid;
        bool act = (e < e_act);
        DST[e] = act ? ei[E + base + e] : 0;
        float d = act ? dist[base + e] : 0.f;
        #pragma unroll
        for (int k=0;k<10;k++){
            float c = 0.7f + (2.5f/9.f)*(float)k;
            float t = (d - c) * 4.5f;
            B[e*H_STR + k] = act ? __expf(-t*t) * (1.f/1.423085244900308f) : 0.f;
        }
        float vx=0.f, vy=0.f, vz=0.f;
        if (act){ vx = rvec[(base+e)*3]; vy = rvec[(base+e)*3+1]; vz = rvec[(base+e)*3+2]; }
        float r   = sqrtf(vx*vx + vy*vy + vz*vz);
        float inv = 1.f / fmaxf(r, 1e-9f);
        float X = vx*inv, Yc = vy*inv, Z = vz*inv;
        float Am[5], Bm[5];
        Am[0] = 1.f; Bm[0] = 0.f;
        #pragma unroll
        for (int m=1;m<=4;m++){
            Am[m] = X*Am[m-1] - Yc*Bm[m-1];
            Bm[m] = X*Bm[m-1] + Yc*Am[m-1];
        }
        float P[5][5];
        P[0][0] = 1.f;
        #pragma unroll
        for (int m=0;m<=4;m++){
            if (m > 0) P[m][m] = -(2.f*m - 1.f)*P[m-1][m-1];
            if (m < 4) P[m+1][m] = (2.f*m + 1.f)*Z*P[m][m];
            #pragma unroll
            for (int l=m+2;l<=4;l++)
                P[l][m] = ((2.f*l - 1.f)*Z*P[l-1][m] - (l + m - 1.f)*P[l-2][m]) / (float)(l - m);
        }
        if (act){
            int idx = 0;
            #pragma unroll
            for (int l=0;l<=4;l++){
                #pragma unroll
                for (int m=-l;m<=l;m++,idx++){
                    int am = (m < 0) ? -m : m;
                    float K = g_K[idx];
                    float val = (m == 0) ? K*P[l][0]
                              : (m > 0)  ? K*P[l][m]*Am[m]
                                         : K*P[l][am]*Bm[am];
                    Ysh[e*Y_STR + idx] = val;
                }
            }
        } else {
            for (int idx=0; idx<25; idx++) Ysh[e*Y_STR + idx] = 0.f;
        }
    }
    for (int i = tid; i < EB*72; i += NTH){
        int e = i/72, dcol = i - e*72;
        float v = 0.f;
        if (e < e_act){ int s = ei[base + e]; v = x[s*72 + dcol]; }
        F[e*F_STR + dcol] = v;
    }
    __syncthreads();

    float wreg[13];
    w3_prefetch(W3, 0, tid, wreg);

    // ---- MLP: h0(B) -> h1(A) -> h2(B) -> h3(A) ----
    mlp_layer(B, A, Wsh, lane, wid16, 10);
    __syncthreads();
    for (int i = tid; i < 10000; i += NTH) Wsh[i] = W1[i]*0.1f;
    __syncthreads();
    mlp_layer(A, B, Wsh, lane, wid16, 100);
    __syncthreads();
    for (int i = tid; i < 10000; i += NTH) Wsh[i] = W2[i]*0.1f;
    __syncthreads();
    mlp_layer(B, A, Wsh, lane, wid16, 100);
    __syncthreads();

    // ---- convert h3 (A, fp32) -> Ah/Al bf16 [128][112] (B region), zero-padded K ----
    for (int i = tid; i < 128*KS; i += NTH){
        int e = i / KS, c = i - e*KS;
        float v = (c < 100) ? A[e*H_STR + c] : 0.f;
        __nv_bfloat16 hv, lv; split_bf16(v, hv, lv);
        Ah[e*KS + c] = hv;
        Al[e*KS + c] = lv;
    }
    __syncthreads();   // A (h3) fully read before B tiles overwrite A region

    // zero Bh/Bl pad cols (k = 100..111); staged cols < 100 are rewritten per instance
    for (int i = tid; i < 64*12; i += NTH){
        int row = i / 12, c = 100 + i % 12;
        Bh[row*KS + c] = __float2bfloat16(0.f);
        Bl[row*KS + c] = __float2bfloat16(0.f);
    }

    // ---- phase B: 19 instances, warp-MMA GEMM + CG contraction ----
    for (int inst = 0; inst < 19; inst++){
        const int lo = c_lo[inst], li = c_li[inst], l = c_l[inst];
        const int P2 = 2*lo+1, Q2 = 2*li+1, Rd = 2*l+1;
        const int foff = c_foff[inst], cgo = c_cgoff[inst];
        const int sbase = (lo == 0) ? 0 : (lo == 1 ? 1 : 4);
        const float nrm = g_norm[lo];

        __syncthreads();   // prior epilogue done (T, B-tiles reusable)

        // stage Bh/Bl from wreg: element (k, c) -> tile[row=c][col=k]
        #pragma unroll
        for (int j=0;j<13;j++){
            int i = tid + j*NTH;
            if (i < 6400){
                int k = i >> 6, c = i & 63;
                __nv_bfloat16 hv, lv; split_bf16(wreg[j], hv, lv);
                Bh[c*KS + k] = hv;
                Bl[c*KS + k] = lv;
            }
        }

        // T[v,p] = sum_q F[v,q] * (sum_r C[p,q,r]*Yl[r])   (4 threads/edge)
        {
            int e  = tid >> 2;
            int ph = tid & 3;
            if (e < e_act && ph < P2){
                float Yl[9];
                for (int r2=0;r2<Rd;r2++) Yl[r2] = Ysh[e*Y_STR + l*l + r2];
                float Fv[8][5];
                #pragma unroll
                for (int v=0;v<8;v++)
                    #pragma unroll
                    for (int q=0;q<5;q++)
                        Fv[v][q] = (q < Q2) ? F[e*F_STR + foff + v*Q2 + q] : 0.f;
                for (int p=ph;p<P2;p+=4){
                    float Gq[5];
                    #pragma unroll
                    for (int q=0;q<5;q++){
                        float s = 0.f;
                        if (q < Q2)
                            for (int r2=0;r2<Rd;r2++) s += CGs[cgo + (p*Q2 + q)*Rd + r2]*Yl[r2];
                        Gq[q] = s;
                    }
                    #pragma unroll
                    for (int v=0;v<8;v++){
                        float t = 0.f;
                        #pragma unroll
                        for (int q=0;q<5;q++) t += Fv[v][q]*Gq[q];
                        T[e*T_STR + v*P2 + p] = t;
                    }
                }
            }
        }

        if (inst + 1 < 19) w3_prefetch(W3, inst + 1, tid, wreg);

        __syncthreads();   // staged B tiles + T visible

        // warp MMA: warp = (m-tile mt, n-half nh); D[128 x 64] = A[128x112] * W^T
        {
            const int mt = wid16 & 7;        // edges 16*mt .. +15
            const int nh = wid16 >> 3;       // cols 32*nh .. +31
            const int g  = lane >> 2;        // group id
            const int tg = lane & 3;         // thread-in-group
            const int ar0 = (16*mt + g)*KS + 2*tg;
            const int ar1 = ar0 + 8*KS;

            float d[4][4];
            #pragma unroll
            for (int nt=0;nt<4;nt++)
                #pragma unroll
                for (int j=0;j<4;j++) d[nt][j] = 0.f;

            #pragma unroll
            for (int ks=0;ks<7;ks++){
                const int k0 = 16*ks;
                uint32_t a0h = *(const uint32_t*)(Ah + ar0 + k0);
                uint32_t a1h = *(const uint32_t*)(Ah + ar1 + k0);
                uint32_t a2h = *(const uint32_t*)(Ah + ar0 + k0 + 8);
                uint32_t a3h = *(const uint32_t*)(Ah + ar1 + k0 + 8);
                uint32_t a0l = *(const uint32_t*)(Al + ar0 + k0);
                uint32_t a1l = *(const uint32_t*)(Al + ar1 + k0);
                uint32_t a2l = *(const uint32_t*)(Al + ar0 + k0 + 8);
                uint32_t a3l = *(const uint32_t*)(Al + ar1 + k0 + 8);
                #pragma unroll
                for (int nt=0;nt<4;nt++){
                    const int bn = (32*nh + 8*nt + g)*KS + 2*tg + k0;
                    uint32_t b0h = *(const uint32_t*)(Bh + bn);
                    uint32_t b1h = *(const uint32_t*)(Bh + bn + 8);
                    uint32_t b0l = *(const uint32_t*)(Bl + bn);
                    uint32_t b1l = *(const uint32_t*)(Bl + bn + 8);
                    MMA_BF16(d[nt], a0h,a1h,a2h,a3h, b0h,b1h);
                    MMA_BF16(d[nt], a0h,a1h,a2h,a3h, b0l,b1l);
                    MMA_BF16(d[nt], a0l,a1l,a2l,a3l, b0h,b1h);
                }
            }

            // write D -> R smem: rows e0/e0+8, cols cb/cb+1 per n-tile
            const int e0 = 16*mt + g;
            #pragma unroll
            for (int nt=0;nt<4;nt++){
                const int cb = 32*nh + 8*nt + 2*tg;
                *(float2*)&R[ e0     *R_STR + cb] = make_float2(d[nt][0], d[nt][1]);
                *(float2*)&R[(e0+8)  *R_STR + cb] = make_float2(d[nt][2], d[nt][3]);
            }
        }
        __syncthreads();   // R complete (all warps' MMAs done)

        // epilogue: msg_acc[uu][sbase+p] += nrm * sum_v R[e][u*8+v] * T[e][v*P2+p]
        {
            const int e  = tid & 127;
            const int wg = tid >> 7;         // 0..3  -> u = 2*wg + uu
            if (e < e_act){
                #pragma unroll
                for (int uu=0; uu<2; uu++){
                    const int u = 2*wg + uu;
                    float4 ra = *(const float4*)&R[e*R_STR + u*8];
                    float4 rb = *(const float4*)&R[e*R_STR + u*8 + 4];
                    float accf[8] = {ra.x, ra.y, ra.z, ra.w, rb.x, rb.y, rb.z, rb.w};
                    for (int p=0;p<P2;p++){
                        float s = 0.f;
                        #pragma unroll
                        for (int v=0;v<8;v++)
                            s += accf[v]*T[e*T_STR + v*P2 + p];
                        msg_acc[uu][sbase + p] += nrm*s;
                    }
                }
            }
        }
    }

    // ---- scatter-add: thread owns edge (tid&127), u = 2*(tid>>7)+uu ----
    {
        int e = tid & 127;
        if (e < e_act){
            int ob = DST[e]*72;
            #pragma unroll
            for (int uu=0; uu<2; uu++){
                int u = 2*(tid >> 7) + uu;
                atomicAdd(&out[ob + u], msg_acc[uu][0]);
                #pragma unroll
                for (int p=0;p<3;p++)
                    atomicAdd(&out[ob + 8 + u*3 + p], msg_acc[uu][1 + p]);
                #pragma unroll
                for (int p=0;p<5;p++)
                    atomicAdd(&out[ob + 32 + u*5 + p], msg_acc[uu][4 + p]);
            }
        }
    }
}

// ---------------- launch ----------------
extern "C" void kernel_launch(void* const* d_in, const int* in_sizes, int n_in,
                              void* d_out, int out_size)
{
    const int*   ei   = (const int*)  d_in[0];
    const float* x    = (const float*)d_in[1];
    const float* dist = (const float*)d_in[2];
    const float* rvec = (const float*)d_in[3];
    const float* W0   = (const float*)d_in[4];
    const float* W1   = (const float*)d_in[5];
    const float* W2   = (const float*)d_in[6];
    const float* W3   = (const float*)d_in[7];
    float* out = (float*)d_out;
    const int E = in_sizes[2];

    size_t smem = (size_t)SM_FLOATS * sizeof(float);
    cudaFuncSetAttribute(tfn_main, cudaFuncAttributeMaxDynamicSharedMemorySize, (int)smem);

    prep_kernel<<<CGB + ZB, 256>>>(out, out_size);
    int nb = (E + EB - 1)/EB;
    tfn_main<<<nb, NTH, smem>>>(ei, x, dist, rvec, W0, W1, W2, W3, out, E);
}